// round 2
// baseline (speedup 1.0000x reference)
#include <cuda_runtime.h>

#define NUM_HEADS 12

constexpr int NBLK = 1184;   // 148 SMs x 8 CTAs — one balanced wave
constexpr int NTHR = 256;

// Scratch for deterministic two-stage reduction (no device mallocs allowed).
__device__ float g_partials[NBLK];

// Natural log via exponent extraction + degree-9 minimax polynomial.
// FMA-pipe only (no MUFU.LG2) — max error ~0.85 ulp (njuffa).
// Valid for normal positive inputs, which p,q always are (>= ~1e-7).
__device__ __forceinline__ float fast_logf(float a) {
    int e = (__float_as_int(a) - 0x3f2aaaab) & 0xff800000;
    float m = __int_as_float(__float_as_int(a) - e);
    float i = (float)e * 1.19209290e-7f;   // e * 2^-23
    m = m - 1.0f;                          // m in [-1/3, 1/3)
    float s = m * m;
    float r =       -0.130310059f;
    float t =        0.140869141f;
    r = fmaf(r, s, -0.121483512f);
    t = fmaf(t, s,  0.139814854f);
    r = fmaf(r, s, -0.166846126f);
    t = fmaf(t, s,  0.200120345f);
    r = fmaf(r, s, -0.249996200f);
    r = fmaf(t, m, r);
    r = fmaf(r, m,  0.333331972f);
    r = fmaf(r, m, -0.500000000f);
    r = fmaf(r, m,  1.000000000f);
    r = r * m;
    r = fmaf(i, 0.693147182f, r);          // + e*ln(2)
    return r;
}

__device__ __forceinline__ float term4(float4 pv, float4 qv, float acc) {
    acc = fmaf(pv.x, fast_logf(pv.x) - fast_logf(qv.x), acc);
    acc = fmaf(pv.y, fast_logf(pv.y) - fast_logf(qv.y), acc);
    acc = fmaf(pv.z, fast_logf(pv.z) - fast_logf(qv.z), acc);
    acc = fmaf(pv.w, fast_logf(pv.w) - fast_logf(qv.w), acc);
    return acc;
}

__global__ void __launch_bounds__(NTHR)
jsd_stage1(const float4* __restrict__ p4, const float4* __restrict__ q4, int n4) {
    float acc0 = 0.0f, acc1 = 0.0f;
    const int stride = gridDim.x * blockDim.x;
    int i = blockIdx.x * blockDim.x + threadIdx.x;

    // 2-way unrolled mainloop: 4 independent 16B loads in flight per iter.
    for (; i + stride < n4; i += 2 * stride) {
        float4 pa = p4[i];
        float4 qa = q4[i];
        float4 pb = p4[i + stride];
        float4 qb = q4[i + stride];
        acc0 = term4(pa, qa, acc0);
        acc1 = term4(pb, qb, acc1);
    }
    if (i < n4) {
        float4 pa = p4[i];
        float4 qa = q4[i];
        acc0 = term4(pa, qa, acc0);
    }
    float acc = acc0 + acc1;

    // Deterministic intra-block reduction: warp shuffle tree + shared tree.
    #pragma unroll
    for (int o = 16; o > 0; o >>= 1)
        acc += __shfl_down_sync(0xffffffffu, acc, o);

    __shared__ float sacc[NTHR / 32];
    if ((threadIdx.x & 31) == 0) sacc[threadIdx.x >> 5] = acc;
    __syncthreads();
    if (threadIdx.x < NTHR / 32) {
        float v = sacc[threadIdx.x];
        #pragma unroll
        for (int o = (NTHR / 32) / 2; o > 0; o >>= 1)
            v += __shfl_down_sync(0xffu, v, o);
        if (threadIdx.x == 0) g_partials[blockIdx.x] = v;
    }
}

// Stage 2: sum NBLK partials in double (deterministic strided + tree), scale.
__global__ void __launch_bounds__(256)
jsd_stage2(float* __restrict__ out) {
    __shared__ double sd[256];
    const int t = threadIdx.x;
    double v = 0.0;
    for (int i = t; i < NBLK; i += 256)
        v += (double)g_partials[i];
    sd[t] = v;
    __syncthreads();
    #pragma unroll
    for (int s = 128; s > 0; s >>= 1) {
        if (t < s) sd[t] += sd[t + s];
        __syncthreads();
    }
    if (t == 0) out[0] = (float)(sd[0] * (0.5 / (double)NUM_HEADS));
}

extern "C" void kernel_launch(void* const* d_in, const int* in_sizes, int n_in,
                              void* d_out, int out_size) {
    const float* p = (const float*)d_in[0];
    const float* q = (const float*)d_in[1];
    const int n  = in_sizes[0];     // 1024*12*4096, divisible by 4
    const int n4 = n >> 2;

    jsd_stage1<<<NBLK, NTHR>>>((const float4*)p, (const float4*)q, n4);
    jsd_stage2<<<1, 256>>>((float*)d_out);
}

// round 5
// speedup vs baseline: 1.1714x; 1.1714x over previous
#include <cuda_runtime.h>

#define NUM_HEADS 12

constexpr int NBLK = 1184;   // 148 SMs x 8 CTAs
constexpr int NTHR = 256;

__device__ float g_partials[NBLK];
__device__ int   g_count = 0;   // reset by last block each launch -> replay-safe

// ln(x) for normal positive x via exponent extraction + degree-8 log1p
// polynomial (Estrin, even/odd split). FMA-pipe only — no MUFU.LG2.
// |error| <= ~9e-6 over the reduced range m in [-1/3, 1/3).
__device__ __forceinline__ float log_poly8(float a) {
    int b = __float_as_int(a);
    int e = (b - 0x3f2aaaab) & 0xff800000;
    float m = __int_as_float(b - e) - 1.0f;     // [-1/3, 1/3)
    float s = m * m;
    // P(m) = A(s) + m*B(s);  log1p(m) = m * P(m)
    float A = fmaf(fmaf(fmaf(0.14285715f, s, 0.20000000f), s, 0.33333334f), s, 1.0f);
    float B = fmaf(fmaf(fmaf(-0.12500000f, s, -0.16666667f), s, -0.25f), s, -0.5f);
    float P = fmaf(m, B, A);
    float r = m * P;
    return fmaf((float)e, 8.26295641e-8f, r);   // + e * ln2 * 2^-23
}

// acc += p * (ln p - ln q), with the two exponent terms folded into one FMA.
__device__ __forceinline__ float jsd_term(float p, float q, float acc) {
    int bp = __float_as_int(p), bq = __float_as_int(q);
    int ep = (bp - 0x3f2aaaab) & 0xff800000;
    int eq = (bq - 0x3f2aaaab) & 0xff800000;
    float mp = __int_as_float(bp - ep) - 1.0f;
    float mq = __int_as_float(bq - eq) - 1.0f;

    float sp = mp * mp, sq = mq * mq;
    float Ap = fmaf(fmaf(fmaf(0.14285715f, sp, 0.2f), sp, 0.33333334f), sp, 1.0f);
    float Bp = fmaf(fmaf(fmaf(-0.125f, sp, -0.16666667f), sp, -0.25f), sp, -0.5f);
    float Aq = fmaf(fmaf(fmaf(0.14285715f, sq, 0.2f), sq, 0.33333334f), sq, 1.0f);
    float Bq = fmaf(fmaf(fmaf(-0.125f, sq, -0.16666667f), sq, -0.25f), sq, -0.5f);
    float Pp = fmaf(mp, Bp, Ap);
    float Pq = fmaf(mq, Bq, Aq);

    float tq = mq * Pq;
    float d  = fmaf(mp, Pp, -tq);                       // log1p(mp) - log1p(mq)
    d = fmaf((float)(ep - eq), 8.26295641e-8f, d);      // + (ep-eq)*ln2*2^-23
    return fmaf(p, d, acc);
}

__global__ void __launch_bounds__(NTHR)
jsd_fused(const float4* __restrict__ p4, const float4* __restrict__ q4,
          int n4, float* __restrict__ out) {
    float acc0 = 0.0f, acc1 = 0.0f;
    const int stride = gridDim.x * blockDim.x;
    int i = blockIdx.x * blockDim.x + threadIdx.x;

    // 2-way unrolled: 4 independent 16B loads in flight per iteration.
    for (; i + stride < n4; i += 2 * stride) {
        float4 pa = p4[i];
        float4 qa = q4[i];
        float4 pb = p4[i + stride];
        float4 qb = q4[i + stride];
        acc0 = jsd_term(pa.x, qa.x, acc0);
        acc0 = jsd_term(pa.y, qa.y, acc0);
        acc0 = jsd_term(pa.z, qa.z, acc0);
        acc0 = jsd_term(pa.w, qa.w, acc0);
        acc1 = jsd_term(pb.x, qb.x, acc1);
        acc1 = jsd_term(pb.y, qb.y, acc1);
        acc1 = jsd_term(pb.z, qb.z, acc1);
        acc1 = jsd_term(pb.w, qb.w, acc1);
    }
    if (i < n4) {
        float4 pa = p4[i];
        float4 qa = q4[i];
        acc0 = jsd_term(pa.x, qa.x, acc0);
        acc0 = jsd_term(pa.y, qa.y, acc0);
        acc0 = jsd_term(pa.z, qa.z, acc0);
        acc0 = jsd_term(pa.w, qa.w, acc0);
    }
    float acc = acc0 + acc1;

    // Deterministic intra-block reduction.
    #pragma unroll
    for (int o = 16; o > 0; o >>= 1)
        acc += __shfl_down_sync(0xffffffffu, acc, o);

    __shared__ float sacc[NTHR / 32];
    if ((threadIdx.x & 31) == 0) sacc[threadIdx.x >> 5] = acc;
    __syncthreads();
    if (threadIdx.x == 0) {
        float v = 0.0f;
        #pragma unroll
        for (int w = 0; w < NTHR / 32; w++) v += sacc[w];
        g_partials[blockIdx.x] = v;
    }

    // ---- last-block final reduction (deterministic: fixed index order) ----
    __shared__ bool is_last;
    __threadfence();
    if (threadIdx.x == 0)
        is_last = (atomicAdd(&g_count, 1) == (int)gridDim.x - 1);
    __syncthreads();
    if (!is_last) return;
    __threadfence();

    __shared__ double sd[NTHR];
    const int t = threadIdx.x;
    double dv = 0.0;
    for (int k = t; k < NBLK; k += NTHR)
        dv += (double)g_partials[k];
    sd[t] = dv;
    __syncthreads();
    #pragma unroll
    for (int s = NTHR / 2; s > 0; s >>= 1) {
        if (t < s) sd[t] += sd[t + s];
        __syncthreads();
    }
    if (t == 0) {
        out[0] = (float)(sd[0] * (0.5 / (double)NUM_HEADS));
        g_count = 0;   // reset for next graph replay
    }
}

extern "C" void kernel_launch(void* const* d_in, const int* in_sizes, int n_in,
                              void* d_out, int out_size) {
    const float* p = (const float*)d_in[0];
    const float* q = (const float*)d_in[1];
    const int n  = in_sizes[0];     // 1024*12*4096, divisible by 4
    const int n4 = n >> 2;

    jsd_fused<<<NBLK, NTHR>>>((const float4*)p, (const float4*)q, n4, (float*)d_out);
}